// round 1
// baseline (speedup 1.0000x reference)
#include <cuda_runtime.h>
#include <cuda_bf16.h>
#include <math.h>

#define Hdim 256
#define Wdim 256
#define HW   65536
#define CC   12
#define BB   8
#define BC   96
#define BIGF 1.0e6f

// Scratch (device globals; no allocation allowed)
__device__ float g_bufA[BC * HW];   // down-dist pos -> g2pos ; later reused for probs
__device__ float g_bufB[BC * HW];   // down-dist neg -> g2neg
__device__ float g_dt  [BC * HW];   // signed distance dt = neg - pos
__device__ int   g_hasfg[BC];
__device__ float g_minmax[BC * 2];
__device__ float g_sums  [BC * 3];  // inter, sumP2, sumD2

// ---------------------------------------------------------------------------
// K1: vertical 1D distance-to-zero per column, for mask m and ~m.
// One block per (b,c); thread w owns column w. Two scans; the down-scan
// partial is staged in g_bufA/g_bufB (each thread reads back only its own
// writes, so no sync needed). Final value written is g^2 (clamped at BIG).
// ---------------------------------------------------------------------------
__global__ void k_vert(const int* __restrict__ targets) {
    const int bc = blockIdx.x;
    const int b  = bc / CC, c = bc % CC;
    const int w  = threadIdx.x;
    const int* tb = targets + b * HW;
    float* A  = g_bufA + bc * HW;
    float* Bv = g_bufB + bc * HW;

    float upP = -BIGF;   // nearest zero of m   (i.e. !fg) at-or-above
    float upN = -BIGF;   // nearest zero of ~m  (i.e.  fg) at-or-above
    int anyfg = 0;
    for (int h = 0; h < Hdim; ++h) {
        const int fg = (tb[h * Wdim + w] == c);
        anyfg |= fg;
        const float fh = (float)h;
        if (!fg) upP = fh;
        if ( fg) upN = fh;
        A [h * Wdim + w] = fh - upP;
        Bv[h * Wdim + w] = fh - upN;
    }
    float dnP = BIGF, dnN = BIGF;
    for (int h = Hdim - 1; h >= 0; --h) {
        const int fg = (tb[h * Wdim + w] == c);
        const float fh = (float)h;
        if (!fg) dnP = fh;
        if ( fg) dnN = fh;
        float gP = fminf(fminf(A [h * Wdim + w], dnP - fh), BIGF);
        float gN = fminf(fminf(Bv[h * Wdim + w], dnN - fh), BIGF);
        A [h * Wdim + w] = gP * gP;
        Bv[h * Wdim + w] = gN * gN;
    }
    __shared__ int sfg;
    if (threadIdx.x == 0) sfg = 0;
    __syncthreads();
    if (anyfg) sfg = 1;                 // benign race: all write 1
    __syncthreads();
    if (threadIdx.x == 0) g_hasfg[bc] = sfg;
}

// ---------------------------------------------------------------------------
// K2: horizontal exact min-plus with parabola, both transforms fused, plus
// dt = sqrt(neg2) - sqrt(pos2). One block per (bc,h) row. Brute O(W^2),
// matching reference semantics exactly (min_k (j-k)^2 + g2[k]).
// ---------------------------------------------------------------------------
__global__ void k_hmin() {
    const int row = blockIdx.x;           // bc*H + h
    const int bc  = row >> 8;
    const int j   = threadIdx.x;

    __shared__ float sP[Wdim];
    __shared__ float sN[Wdim];
    sP[j] = g_bufA[row * Wdim + j];
    sN[j] = g_bufB[row * Wdim + j];
    const int hf = g_hasfg[bc];
    __syncthreads();

    // two independent accumulator pairs to break the fmin dependency chain
    float mP0 = 3.0e12f, mP1 = 3.0e12f;
    float mN0 = 3.0e12f, mN1 = 3.0e12f;
    float dk0 = (float)j;        // j - k for even k
    float dk1 = (float)(j - 1);  // j - k for odd k
    #pragma unroll 4
    for (int k = 0; k < Wdim; k += 2) {
        mP0 = fminf(mP0, fmaf(dk0, dk0, sP[k]));
        mN0 = fminf(mN0, fmaf(dk0, dk0, sN[k]));
        mP1 = fminf(mP1, fmaf(dk1, dk1, sP[k + 1]));
        mN1 = fminf(mN1, fmaf(dk1, dk1, sN[k + 1]));
        dk0 -= 2.0f;
        dk1 -= 2.0f;
    }
    const float mP = fminf(mP0, mP1);
    const float mN = fminf(mN0, mN1);
    float dt = sqrtf(mN) - sqrtf(mP);
    if (!hf) dt = 0.0f;
    g_dt[row * Wdim + j] = dt;
}

// ---------------------------------------------------------------------------
// K3: softmax over C per pixel; probs stored into g_bufA (free after K2).
// One block per (b,h); thread w.
// ---------------------------------------------------------------------------
__global__ void k_probs(const float* __restrict__ logits) {
    const int bh = blockIdx.x;             // b*H + h
    const int b  = bh >> 8;
    const int h  = bh & 255;
    const int w  = threadIdx.x;
    const int boff = b * CC * HW + h * Wdim + w;

    float l[CC];
    float mx = -1e30f;
    #pragma unroll
    for (int c = 0; c < CC; ++c) { l[c] = logits[boff + c * HW]; mx = fmaxf(mx, l[c]); }
    float s = 0.0f;
    #pragma unroll
    for (int c = 0; c < CC; ++c) { l[c] = __expf(l[c] - mx); s += l[c]; }
    const float r = 1.0f / s;
    #pragma unroll
    for (int c = 0; c < CC; ++c) g_bufA[boff + c * HW] = l[c] * r;
}

// ---------------------------------------------------------------------------
// K4: per-(b,c) min/max of dt over H*W. One block per bc.
// ---------------------------------------------------------------------------
__global__ void k_minmax() {
    const int bc = blockIdx.x;
    const float* D = g_dt + bc * HW;
    float mn = 1e30f, mx = -1e30f;
    for (int i = threadIdx.x; i < HW; i += 256) {
        const float v = D[i];
        mn = fminf(mn, v);
        mx = fmaxf(mx, v);
    }
    #pragma unroll
    for (int o = 16; o; o >>= 1) {
        mn = fminf(mn, __shfl_xor_sync(0xffffffffu, mn, o));
        mx = fmaxf(mx, __shfl_xor_sync(0xffffffffu, mx, o));
    }
    __shared__ float smn[8], smx[8];
    if ((threadIdx.x & 31) == 0) { smn[threadIdx.x >> 5] = mn; smx[threadIdx.x >> 5] = mx; }
    __syncthreads();
    if (threadIdx.x == 0) {
        float a = smn[0], bx = smx[0];
        #pragma unroll
        for (int i = 1; i < 8; ++i) { a = fminf(a, smn[i]); bx = fmaxf(bx, smx[i]); }
        g_minmax[bc * 2]     = a;
        g_minmax[bc * 2 + 1] = bx;
    }
}

// ---------------------------------------------------------------------------
// K5: per-(b,c) fused sums: inter = sum p*dtn, sum p^2, sum dtn^2.
// One block per bc; probs in g_bufA, dt in g_dt.
// ---------------------------------------------------------------------------
__global__ void k_sums() {
    const int bc = blockIdx.x;
    const float dmin = g_minmax[bc * 2];
    const float dmax = g_minmax[bc * 2 + 1];
    const float inv  = 1.0f / (dmax - dmin + 1e-8f);
    const float* P = g_bufA + bc * HW;
    const float* D = g_dt   + bc * HW;
    float sI = 0.0f, sP2 = 0.0f, sD2 = 0.0f;
    for (int i = threadIdx.x; i < HW; i += 256) {
        const float p   = P[i];
        const float dtn = (D[i] - dmin) * inv;
        sI  = fmaf(p, dtn, sI);
        sP2 = fmaf(p, p,   sP2);
        sD2 = fmaf(dtn, dtn, sD2);
    }
    #pragma unroll
    for (int o = 16; o; o >>= 1) {
        sI  += __shfl_xor_sync(0xffffffffu, sI,  o);
        sP2 += __shfl_xor_sync(0xffffffffu, sP2, o);
        sD2 += __shfl_xor_sync(0xffffffffu, sD2, o);
    }
    __shared__ float sh[3][8];
    if ((threadIdx.x & 31) == 0) {
        const int wi = threadIdx.x >> 5;
        sh[0][wi] = sI; sh[1][wi] = sP2; sh[2][wi] = sD2;
    }
    __syncthreads();
    if (threadIdx.x == 0) {
        float a = 0.0f, b = 0.0f, c = 0.0f;
        #pragma unroll
        for (int i = 0; i < 8; ++i) { a += sh[0][i]; b += sh[1][i]; c += sh[2][i]; }
        g_sums[bc * 3]     = a;
        g_sums[bc * 3 + 1] = b;
        g_sums[bc * 3 + 2] = c;
    }
}

// ---------------------------------------------------------------------------
// K6: final dice mean over 96 (b,c) pairs.
// ---------------------------------------------------------------------------
__global__ void k_final(float* __restrict__ out) {
    __shared__ float s[128];
    const int i = threadIdx.x;
    float li = 0.0f;
    if (i < BC) {
        const float I  = g_sums[i * 3];
        const float P2 = g_sums[i * 3 + 1];
        const float D2 = g_sums[i * 3 + 2];
        const float dice = 2.0f * I / (P2 + D2 + 1e-6f);
        li = 1.0f - dice;
    }
    s[i] = li;
    __syncthreads();
    #pragma unroll
    for (int o = 64; o; o >>= 1) {
        if (i < o) s[i] += s[i + o];
        __syncthreads();
    }
    if (i == 0) out[0] = s[0] / (float)BC;
}

extern "C" void kernel_launch(void* const* d_in, const int* in_sizes, int n_in,
                              void* d_out, int out_size) {
    const float* logits  = (const float*)d_in[0];
    const int*   targets = (const int*)d_in[1];
    float* out = (float*)d_out;

    k_vert  <<<BC, 256>>>(targets);
    k_hmin  <<<BC * Hdim, 256>>>();
    k_probs <<<BB * Hdim, 256>>>(logits);
    k_minmax<<<BC, 256>>>();
    k_sums  <<<BC, 256>>>();
    k_final <<<1, 128>>>(out);
}

// round 2
// speedup vs baseline: 1.2027x; 1.2027x over previous
#include <cuda_runtime.h>
#include <cuda_bf16.h>
#include <math.h>

#define Hdim 256
#define Wdim 256
#define HW   65536
#define CC   12
#define BB   8
#define BC   96
#define BIGF 1.0e6f

// Scratch (device globals; no allocation allowed)
__device__ float g_bufA[BC * HW];   // vertical g^2 for mask m
__device__ float g_bufB[BC * HW];   // vertical g^2 for ~m
__device__ float g_dt  [BC * HW];   // signed distance dt = neg - pos
__device__ int   g_hasfg[BC];
__device__ float g_minmax[BC * 2];  // (min, max) per bc  -- atomically reduced
__device__ float g_sums  [BC * 3];  // inter, sumP2, sumD2 -- atomically accumulated

__device__ __forceinline__ float atomicMinFloat(float* a, float v) {
    return (v >= 0.0f)
        ? __int_as_float(atomicMin((int*)a, __float_as_int(v)))
        : __uint_as_float(atomicMax((unsigned*)a, __float_as_uint(v)));
}
__device__ __forceinline__ float atomicMaxFloat(float* a, float v) {
    return (v >= 0.0f)
        ? __int_as_float(atomicMax((int*)a, __float_as_int(v)))
        : __uint_as_float(atomicMin((unsigned*)a, __float_as_uint(v)));
}

// ---------------------------------------------------------------------------
// K0: reset the atomic accumulators (device globals persist across graph replays)
// ---------------------------------------------------------------------------
__global__ void k_init() {
    const int i = threadIdx.x;
    if (i < BC) {
        g_minmax[i * 2]     =  1e30f;
        g_minmax[i * 2 + 1] = -1e30f;
    }
    if (i < BC * 3) {
        g_sums[i] = 0.0f;
    }
}

// ---------------------------------------------------------------------------
// K1: vertical 1D distance-to-zero per column, for mask m and ~m.
// One block per (b,c); thread w owns column w. Pass 1 scans down storing
// fh-up; pass 2 scans up, recovers fg from staged value (aP==0 <=> bg),
// combines, writes g^2 (clamped at BIG).
// ---------------------------------------------------------------------------
__global__ void k_vert(const int* __restrict__ targets) {
    const int bc = blockIdx.x;
    const int b  = bc / CC, c = bc % CC;
    const int w  = threadIdx.x;
    const int* tb = targets + b * HW;
    float* A  = g_bufA + bc * HW;
    float* Bv = g_bufB + bc * HW;

    float upP = -BIGF;   // nearest zero of m  (bg pixel) at-or-above
    float upN = -BIGF;   // nearest zero of ~m (fg pixel) at-or-above
    int anyfg = 0;
    #pragma unroll 4
    for (int h = 0; h < Hdim; ++h) {
        const int fg = (tb[h * Wdim + w] == c);
        anyfg |= fg;
        const float fh = (float)h;
        if (!fg) upP = fh;
        if ( fg) upN = fh;
        A [h * Wdim + w] = fh - upP;   // ==0 iff bg pixel
        Bv[h * Wdim + w] = fh - upN;   // ==0 iff fg pixel
    }
    float dnP = BIGF, dnN = BIGF;
    #pragma unroll 4
    for (int h = Hdim - 1; h >= 0; --h) {
        const float aP = A [h * Wdim + w];
        const float aN = Bv[h * Wdim + w];
        const int fg = (aP != 0.0f);
        const float fh = (float)h;
        if (!fg) dnP = fh;
        if ( fg) dnN = fh;
        float gP = fminf(fminf(aP, dnP - fh), BIGF);
        float gN = fminf(fminf(aN, dnN - fh), BIGF);
        A [h * Wdim + w] = gP * gP;
        Bv[h * Wdim + w] = gN * gN;
    }
    __shared__ int sfg;
    if (threadIdx.x == 0) sfg = 0;
    __syncthreads();
    if (anyfg) sfg = 1;                 // benign race: all write 1
    __syncthreads();
    if (threadIdx.x == 0) g_hasfg[bc] = sfg;
}

// ---------------------------------------------------------------------------
// K2: horizontal exact min-plus with parabola + signed dt + fused min/max.
// One block per (bc,h) row; thread j computes output pixel j.
// Selection trick: each pixel needs only ONE transform (fg -> P, bg -> N).
// Algebra trick: (j-k)^2 + g2 = j^2 + (-2j*k + (k^2+g2)); with u[k]=k^2+g2
// staged in shared and the k-loop fully unrolled, each k is one
// FFMA (immediate multiplier) + one FMNMX; LDS.128 amortized over 4 k.
// ---------------------------------------------------------------------------
__global__ void __launch_bounds__(256) k_hmin() {
    const int row = blockIdx.x;           // bc*H + h
    const int bc  = row >> 8;
    const int j   = threadIdx.x;

    // sP at [0..255], sN at [260..515]: both 16B-aligned, LDS.128 from the
    // two bases hits disjoint banks (260 mod 32 == 4) -> conflict-free.
    __shared__ __align__(16) float sh[520];
    const float jf = (float)j;
    const float vP = g_bufA[row * Wdim + j];
    const float vN = g_bufB[row * Wdim + j];
    const float k2 = jf * jf;
    sh[j]       = k2 + vP;                // u_P[k] = k^2 + g2P[k]
    sh[260 + j] = k2 + vN;                // u_N[k]
    const bool fg = (vP != 0.0f);         // vertical gP == 0  <=>  bg pixel
    const int  hf = g_hasfg[bc];
    __syncthreads();

    const float* base = fg ? sh : (sh + 260);
    const float c = -2.0f * jf;

    float m0 = 3.0e12f, m1 = 3.0e12f, m2 = 3.0e12f, m3 = 3.0e12f;
    #pragma unroll
    for (int k = 0; k < Wdim; k += 4) {
        const float4 t = *(const float4*)(base + k);
        m0 = fminf(m0, fmaf(c, (float)(k),     t.x));
        m1 = fminf(m1, fmaf(c, (float)(k + 1), t.y));
        m2 = fminf(m2, fmaf(c, (float)(k + 2), t.z));
        m3 = fminf(m3, fmaf(c, (float)(k + 3), t.w));
    }
    const float m = fmaf(jf, jf, fminf(fminf(m0, m1), fminf(m2, m3)));
    float dt = fg ? -sqrtf(m) : sqrtf(m);
    if (!hf) dt = 0.0f;
    g_dt[row * Wdim + j] = dt;

    // fused per-(b,c) min/max: block reduce then one atomic pair per block
    float mn = dt, mx = dt;
    #pragma unroll
    for (int o = 16; o; o >>= 1) {
        mn = fminf(mn, __shfl_xor_sync(0xffffffffu, mn, o));
        mx = fmaxf(mx, __shfl_xor_sync(0xffffffffu, mx, o));
    }
    __shared__ float smn[8], smx[8];
    if ((j & 31) == 0) { smn[j >> 5] = mn; smx[j >> 5] = mx; }
    __syncthreads();
    if (j == 0) {
        float a = smn[0], b = smx[0];
        #pragma unroll
        for (int i = 1; i < 8; ++i) { a = fminf(a, smn[i]); b = fmaxf(b, smx[i]); }
        atomicMinFloat(&g_minmax[bc * 2],     a);
        atomicMaxFloat(&g_minmax[bc * 2 + 1], b);
    }
}

// ---------------------------------------------------------------------------
// K3: fused softmax + normalization + dice sums. Probs are never stored.
// Grid: (b, 32 row-groups) = 256 blocks; each thread handles 8 pixels
// (one column across 8 rows) and accumulates 3 sums per class.
// ---------------------------------------------------------------------------
__global__ void __launch_bounds__(256) k_sums(const float* __restrict__ logits) {
    const int blk = blockIdx.x;            // b*32 + rowgroup
    const int b   = blk >> 5;
    const int h0  = (blk & 31) * 8;
    const int w   = threadIdx.x;

    __shared__ float sdm[CC], sinv[CC];
    if (w < CC) {
        const float dmin = g_minmax[(b * CC + w) * 2];
        const float dmax = g_minmax[(b * CC + w) * 2 + 1];
        sdm[w]  = dmin;
        sinv[w] = 1.0f / (dmax - dmin + 1e-8f);
    }
    __syncthreads();

    float aI[CC], aP2[CC], aD2[CC];
    #pragma unroll
    for (int c = 0; c < CC; ++c) { aI[c] = 0.0f; aP2[c] = 0.0f; aD2[c] = 0.0f; }

    const int boffL = b * CC * HW;
    for (int r = 0; r < 8; ++r) {
        const int pix = (h0 + r) * Wdim + w;
        float l[CC];
        float mxl = -1e30f;
        #pragma unroll
        for (int c = 0; c < CC; ++c) {
            l[c] = logits[boffL + c * HW + pix];
            mxl = fmaxf(mxl, l[c]);
        }
        float s = 0.0f;
        #pragma unroll
        for (int c = 0; c < CC; ++c) { l[c] = __expf(l[c] - mxl); s += l[c]; }
        const float rs = 1.0f / s;
        #pragma unroll
        for (int c = 0; c < CC; ++c) {
            const float p   = l[c] * rs;
            const float d   = g_dt[boffL + c * HW + pix];
            const float dtn = (d - sdm[c]) * sinv[c];
            aI [c] = fmaf(p,   dtn, aI [c]);
            aP2[c] = fmaf(p,   p,   aP2[c]);
            aD2[c] = fmaf(dtn, dtn, aD2[c]);
        }
    }

    // warp reduce all 36 partials, stage per-warp, block reduce, atomic add
    #pragma unroll
    for (int c = 0; c < CC; ++c) {
        #pragma unroll
        for (int o = 16; o; o >>= 1) {
            aI [c] += __shfl_xor_sync(0xffffffffu, aI [c], o);
            aP2[c] += __shfl_xor_sync(0xffffffffu, aP2[c], o);
            aD2[c] += __shfl_xor_sync(0xffffffffu, aD2[c], o);
        }
    }
    __shared__ float sred[36][8];
    const int lane = w & 31, wi = w >> 5;
    if (lane == 0) {
        #pragma unroll
        for (int c = 0; c < CC; ++c) {
            sred[c * 3 + 0][wi] = aI [c];
            sred[c * 3 + 1][wi] = aP2[c];
            sred[c * 3 + 2][wi] = aD2[c];
        }
    }
    __syncthreads();
    if (w < 36) {
        float acc = 0.0f;
        #pragma unroll
        for (int i = 0; i < 8; ++i) acc += sred[w][i];
        const int c    = w / 3;
        const int comp = w - c * 3;
        atomicAdd(&g_sums[(b * CC + c) * 3 + comp], acc);
    }
}

// ---------------------------------------------------------------------------
// K4: final dice mean over 96 (b,c) pairs.
// ---------------------------------------------------------------------------
__global__ void k_final(float* __restrict__ out) {
    __shared__ float s[128];
    const int i = threadIdx.x;
    float li = 0.0f;
    if (i < BC) {
        const float I  = g_sums[i * 3];
        const float P2 = g_sums[i * 3 + 1];
        const float D2 = g_sums[i * 3 + 2];
        li = 1.0f - 2.0f * I / (P2 + D2 + 1e-6f);
    }
    s[i] = li;
    __syncthreads();
    #pragma unroll
    for (int o = 64; o; o >>= 1) {
        if (i < o) s[i] += s[i + o];
        __syncthreads();
    }
    if (i == 0) out[0] = s[0] / (float)BC;
}

extern "C" void kernel_launch(void* const* d_in, const int* in_sizes, int n_in,
                              void* d_out, int out_size) {
    const float* logits  = (const float*)d_in[0];
    const int*   targets = (const int*)d_in[1];
    float* out = (float*)d_out;

    k_init <<<1, 512>>>();
    k_vert <<<BC, 256>>>(targets);
    k_hmin <<<BC * Hdim, 256>>>();
    k_sums <<<BB * 32, 256>>>(logits);
    k_final<<<1, 128>>>(out);
}

// round 3
// speedup vs baseline: 3.7460x; 3.1147x over previous
#include <cuda_runtime.h>
#include <cuda_bf16.h>
#include <math.h>

#define Hdim 256
#define Wdim 256
#define HW   65536
#define CC   12
#define BB   8
#define BC   96
#define SENT 600        // u16 sentinel: 600^2 = 360000 > max real d^2 (130050)

// Scratch (device globals; no allocation allowed)
__device__ unsigned short g_vP[BC * HW]; // vertical 1D distance for mask m   (0 <=> bg pixel)
__device__ unsigned short g_vN[BC * HW]; // vertical 1D distance for mask ~m  (0 <=> fg pixel)
__device__ float g_dt  [BC * HW];        // signed distance dt = neg - pos
__device__ int   g_hasfg[BC];
__device__ float g_minmax[BC * 2];       // (min, max) per bc  -- atomically reduced
__device__ float g_sums  [BC * 3];       // inter, sumP2, sumD2 -- atomically accumulated

__device__ __forceinline__ float atomicMinFloat(float* a, float v) {
    return (v >= 0.0f)
        ? __int_as_float(atomicMin((int*)a, __float_as_int(v)))
        : __uint_as_float(atomicMax((unsigned*)a, __float_as_uint(v)));
}
__device__ __forceinline__ float atomicMaxFloat(float* a, float v) {
    return (v >= 0.0f)
        ? __int_as_float(atomicMax((int*)a, __float_as_int(v)))
        : __uint_as_float(atomicMin((unsigned*)a, __float_as_uint(v)));
}

// ---------------------------------------------------------------------------
// K0: reset atomic accumulators (device globals persist across graph replays)
// ---------------------------------------------------------------------------
__global__ void k_init() {
    const int i = threadIdx.x;
    if (i < BC) {
        g_minmax[i * 2]     =  1e30f;
        g_minmax[i * 2 + 1] = -1e30f;
    }
    if (i < BC * 3) g_sums[i] = 0.0f;
}

// ---------------------------------------------------------------------------
// K1: vertical 1D distance-to-zero per column (u16, clamped at SENT).
// One block per (b,c); thread w owns column w. Pass 1 down-scan stages
// h-up (clamped); pass 2 up-scan combines with down distance.
// Staged value == 0  <=>  pixel is a zero of that mask.
// ---------------------------------------------------------------------------
__global__ void k_vert(const int* __restrict__ targets) {
    const int bc = blockIdx.x;
    const int b  = bc / CC, c = bc % CC;
    const int w  = threadIdx.x;
    const int* tb = targets + b * HW;
    unsigned short* P = g_vP + bc * HW;
    unsigned short* N = g_vN + bc * HW;

    int upP = -100000;   // last bg row seen (zero of m)
    int upN = -100000;   // last fg row seen (zero of ~m)
    int anyfg = 0;
    #pragma unroll 8
    for (int h = 0; h < Hdim; ++h) {
        const int fg = (tb[h * Wdim + w] == c);
        anyfg |= fg;
        if (!fg) upP = h;
        if ( fg) upN = h;
        P[h * Wdim + w] = (unsigned short)min(h - upP, SENT);
        N[h * Wdim + w] = (unsigned short)min(h - upN, SENT);
    }
    int dnP = 100000, dnN = 100000;
    #pragma unroll 8
    for (int h = Hdim - 1; h >= 0; --h) {
        const int aP = P[h * Wdim + w];
        const int aN = N[h * Wdim + w];
        const int fg = (aP != 0);       // staged pos-dist 0 <=> bg pixel
        if (!fg) dnP = h;
        if ( fg) dnN = h;
        P[h * Wdim + w] = (unsigned short)min(min(aP, dnP - h), SENT);
        N[h * Wdim + w] = (unsigned short)min(min(aN, dnN - h), SENT);
    }
    __shared__ int sfg;
    if (threadIdx.x == 0) sfg = 0;
    __syncthreads();
    if (anyfg) sfg = 1;                 // benign race: all write 1
    __syncthreads();
    if (threadIdx.x == 0) g_hasfg[bc] = sfg;
}

// ---------------------------------------------------------------------------
// K2: horizontal exact min-plus via outward search with early exit.
//   d2(j) = min_k (j-k)^2 + g2[k];  scan r=1,2,... from k=j, stop when
//   r^2 >= best  (remaining terms >= r^2 >= best  -> exact).
// Each pixel needs only ONE transform (fg pixel -> P, bg pixel -> N).
// Shared arrays padded 256 each side with +INF so the loop is branch-light.
// Fused per-(b,c) min/max reduction at the end.
// ---------------------------------------------------------------------------
__global__ void __launch_bounds__(256) k_hmin() {
    const int row = blockIdx.x;            // bc*H + h
    const int bc  = row >> 8;
    const int j   = threadIdx.x;

    __shared__ float shP[768];             // [256..512) real, pads = +INF
    __shared__ float shN[768];
    const int vP = g_vP[row * Wdim + j];
    const int vN = g_vN[row * Wdim + j];
    const float fP = (float)vP, fN = (float)vN;
    shP[j]       = 1.0e9f;  shN[j]       = 1.0e9f;
    shP[256 + j] = fP * fP; shN[256 + j] = fN * fN;
    shP[512 + j] = 1.0e9f;  shN[512 + j] = 1.0e9f;
    const bool fg = (vP != 0);
    const int  hf = g_hasfg[bc];
    __syncthreads();

    const float* s = (fg ? shP : shN) + 256 + j;
    float best = s[0];
    float rr = 1.0f, dr = 3.0f;            // rr = r^2, incremental
    #pragma unroll 1
    for (int r = 1; r < 256; ++r) {
        if (rr >= best) break;
        best = fminf(best, rr + s[-r]);
        best = fminf(best, rr + s[ r]);
        rr += dr; dr += 2.0f;
    }
    float dt = fg ? -sqrtf(best) : sqrtf(best);
    if (!hf) dt = 0.0f;
    g_dt[row * Wdim + j] = dt;

    // fused per-(b,c) min/max: block reduce then one atomic pair per block
    float mn = dt, mx = dt;
    #pragma unroll
    for (int o = 16; o; o >>= 1) {
        mn = fminf(mn, __shfl_xor_sync(0xffffffffu, mn, o));
        mx = fmaxf(mx, __shfl_xor_sync(0xffffffffu, mx, o));
    }
    __shared__ float smn[8], smx[8];
    if ((j & 31) == 0) { smn[j >> 5] = mn; smx[j >> 5] = mx; }
    __syncthreads();
    if (j == 0) {
        float a = smn[0], b = smx[0];
        #pragma unroll
        for (int i = 1; i < 8; ++i) { a = fminf(a, smn[i]); b = fmaxf(b, smx[i]); }
        atomicMinFloat(&g_minmax[bc * 2],     a);
        atomicMaxFloat(&g_minmax[bc * 2 + 1], b);
    }
}

// ---------------------------------------------------------------------------
// K3: fused softmax + normalization + dice sums. Probs are never stored.
// Grid: (b, 32 row-groups) = 256 blocks; each thread handles 8 pixels
// (one column across 8 rows) and accumulates 3 sums per class.
// ---------------------------------------------------------------------------
__global__ void __launch_bounds__(256) k_sums(const float* __restrict__ logits) {
    const int blk = blockIdx.x;            // b*32 + rowgroup
    const int b   = blk >> 5;
    const int h0  = (blk & 31) * 8;
    const int w   = threadIdx.x;

    __shared__ float sdm[CC], sinv[CC];
    if (w < CC) {
        const float dmin = g_minmax[(b * CC + w) * 2];
        const float dmax = g_minmax[(b * CC + w) * 2 + 1];
        sdm[w]  = dmin;
        sinv[w] = 1.0f / (dmax - dmin + 1e-8f);
    }
    __syncthreads();

    float aI[CC], aP2[CC], aD2[CC];
    #pragma unroll
    for (int c = 0; c < CC; ++c) { aI[c] = 0.0f; aP2[c] = 0.0f; aD2[c] = 0.0f; }

    const int boffL = b * CC * HW;
    for (int r = 0; r < 8; ++r) {
        const int pix = (h0 + r) * Wdim + w;
        float l[CC];
        float mxl = -1e30f;
        #pragma unroll
        for (int c = 0; c < CC; ++c) {
            l[c] = logits[boffL + c * HW + pix];
            mxl = fmaxf(mxl, l[c]);
        }
        float s = 0.0f;
        #pragma unroll
        for (int c = 0; c < CC; ++c) { l[c] = __expf(l[c] - mxl); s += l[c]; }
        const float rs = 1.0f / s;
        #pragma unroll
        for (int c = 0; c < CC; ++c) {
            const float p   = l[c] * rs;
            const float d   = g_dt[boffL + c * HW + pix];
            const float dtn = (d - sdm[c]) * sinv[c];
            aI [c] = fmaf(p,   dtn, aI [c]);
            aP2[c] = fmaf(p,   p,   aP2[c]);
            aD2[c] = fmaf(dtn, dtn, aD2[c]);
        }
    }

    #pragma unroll
    for (int c = 0; c < CC; ++c) {
        #pragma unroll
        for (int o = 16; o; o >>= 1) {
            aI [c] += __shfl_xor_sync(0xffffffffu, aI [c], o);
            aP2[c] += __shfl_xor_sync(0xffffffffu, aP2[c], o);
            aD2[c] += __shfl_xor_sync(0xffffffffu, aD2[c], o);
        }
    }
    __shared__ float sred[36][8];
    const int lane = w & 31, wi = w >> 5;
    if (lane == 0) {
        #pragma unroll
        for (int c = 0; c < CC; ++c) {
            sred[c * 3 + 0][wi] = aI [c];
            sred[c * 3 + 1][wi] = aP2[c];
            sred[c * 3 + 2][wi] = aD2[c];
        }
    }
    __syncthreads();
    if (w < 36) {
        float acc = 0.0f;
        #pragma unroll
        for (int i = 0; i < 8; ++i) acc += sred[w][i];
        const int c    = w / 3;
        const int comp = w - c * 3;
        atomicAdd(&g_sums[(b * CC + c) * 3 + comp], acc);
    }
}

// ---------------------------------------------------------------------------
// K4: final dice mean over 96 (b,c) pairs.
// ---------------------------------------------------------------------------
__global__ void k_final(float* __restrict__ out) {
    __shared__ float s[128];
    const int i = threadIdx.x;
    float li = 0.0f;
    if (i < BC) {
        const float I  = g_sums[i * 3];
        const float P2 = g_sums[i * 3 + 1];
        const float D2 = g_sums[i * 3 + 2];
        li = 1.0f - 2.0f * I / (P2 + D2 + 1e-6f);
    }
    s[i] = li;
    __syncthreads();
    #pragma unroll
    for (int o = 64; o; o >>= 1) {
        if (i < o) s[i] += s[i + o];
        __syncthreads();
    }
    if (i == 0) out[0] = s[0] / (float)BC;
}

extern "C" void kernel_launch(void* const* d_in, const int* in_sizes, int n_in,
                              void* d_out, int out_size) {
    const float* logits  = (const float*)d_in[0];
    const int*   targets = (const int*)d_in[1];
    float* out = (float*)d_out;

    k_init <<<1, 512>>>();
    k_vert <<<BC, 256>>>(targets);
    k_hmin <<<BC * Hdim, 256>>>();
    k_sums <<<BB * 32, 256>>>(logits);
    k_final<<<1, 128>>>(out);
}